// round 3
// baseline (speedup 1.0000x reference)
#include <cuda_runtime.h>
#include <cuda_bf16.h>
#include <math.h>

#define N_NODES 50000
#define N_EDGES 800000
#define FEAT    128
#define HID     64
#define TYPE_NUM 10

// ---------------- scratch buffers (float4-typed => 16B alignment) -----------
__device__ float4 g_y  [N_NODES * HID / 4];   // rel-transformed features
__device__ float4 g_rA [N_NODES * HID / 4];   // root part / layer output (ping)
__device__ float4 g_rB [N_NODES * HID / 4];   // root part / layer output (pong)
__device__ float4 g_agg[N_NODES * HID / 4];   // aggregation target

// ---------------------------------------------------------------------------
// Dual GEMM: y = in @ Wrel, r = in @ Wroot   (in: [N,K], W: [K,64])
// Also zeroes the agg rows for this block (fused so no separate memset pass).
// Block: 256 threads, 64-row tile. Each thread: 1 col x 16 rows x 2 outputs.
// ---------------------------------------------------------------------------
template<int K>
__global__ void __launch_bounds__(256) dual_gemm(
    const float* __restrict__ in, const float* __restrict__ Wr,
    const float* __restrict__ Wo, float* __restrict__ y,
    float* __restrict__ r, float* __restrict__ agg, int N)
{
    __shared__ float sIn[32][68];   // transposed [k][row], +4 pad keeps float4 alignment
    __shared__ float sWr[32][64];
    __shared__ float sWo[32][64];

    const int tid  = threadIdx.x;
    const int col  = tid & 63;
    const int rg   = tid >> 6;          // 0..3 -> rows rg*16 .. rg*16+15
    const int row0 = blockIdx.x * 64;

    // zero agg rows of this tile
    {
        int limit = (N - row0) * HID;
        if (limit > 64 * HID) limit = 64 * HID;
        int base = row0 * HID;
        for (int i = tid; i < limit; i += 256) agg[base + i] = 0.f;
    }

    float accY[16], accR[16];
    #pragma unroll
    for (int j = 0; j < 16; j++) { accY[j] = 0.f; accR[j] = 0.f; }

    for (int kc = 0; kc < K; kc += 32) {
        __syncthreads();
        // load input tile transposed: sIn[k][row]
        #pragma unroll
        for (int e = 0; e < 8; e++) {
            int linear = tid + e * 256;         // 0..2047
            int rl = linear >> 5;               // 0..63
            int kl = linear & 31;
            int grow = row0 + rl;
            sIn[kl][rl] = (grow < N) ? in[(size_t)grow * K + kc + kl] : 0.f;
        }
        // load weight tiles
        #pragma unroll
        for (int e = 0; e < 8; e++) {
            int linear = tid + e * 256;
            int kk = linear >> 6;
            int cc = linear & 63;
            sWr[kk][cc] = Wr[(size_t)(kc + kk) * HID + cc];
            sWo[kk][cc] = Wo[(size_t)(kc + kk) * HID + cc];
        }
        __syncthreads();

        #pragma unroll
        for (int k = 0; k < 32; k++) {
            float wr = sWr[k][col];
            float wo = sWo[k][col];
            const float4* rowp = (const float4*)(&sIn[k][rg * 16]);
            #pragma unroll
            for (int q = 0; q < 4; q++) {
                float4 a = rowp[q];
                accY[q*4+0] += a.x * wr;  accR[q*4+0] += a.x * wo;
                accY[q*4+1] += a.y * wr;  accR[q*4+1] += a.y * wo;
                accY[q*4+2] += a.z * wr;  accR[q*4+2] += a.z * wo;
                accY[q*4+3] += a.w * wr;  accR[q*4+3] += a.w * wo;
            }
        }
    }

    #pragma unroll
    for (int j = 0; j < 16; j++) {
        int grow = row0 + rg * 16 + j;
        if (grow < N) {
            y[(size_t)grow * HID + col] = accY[j];
            r[(size_t)grow * HID + col] = accR[j];
        }
    }
}

// ---------------------------------------------------------------------------
// Edge scatter: agg[dst] += y[src]   (vector float4 atomics, 16 threads/edge)
// Edge indices are INT32 (JAX x64 disabled).
// ---------------------------------------------------------------------------
__global__ void __launch_bounds__(256) scatter_edges(
    const float4* __restrict__ y, const int* __restrict__ ei,
    float4* __restrict__ agg, int E)
{
    int t = blockIdx.x * blockDim.x + threadIdx.x;
    int e = t >> 4;
    if (e >= E) return;
    int lane = t & 15;
    int s = ei[e];
    int d = ei[E + e];
    float4 v = y[(size_t)s * (HID / 4) + lane];
    atomicAdd(&agg[(size_t)d * (HID / 4) + lane], v);
}

// ---------------------------------------------------------------------------
// h = relu(agg + r)  written in place into r
// ---------------------------------------------------------------------------
__global__ void __launch_bounds__(256) relu_add(
    const float4* __restrict__ agg, float4* __restrict__ r, int n4)
{
    int i = blockIdx.x * blockDim.x + threadIdx.x;
    if (i >= n4) return;
    float4 a = agg[i];
    float4 b = r[i];
    b.x = fmaxf(a.x + b.x, 0.f);
    b.y = fmaxf(a.y + b.y, 0.f);
    b.z = fmaxf(a.z + b.z, 0.f);
    b.w = fmaxf(a.w + b.w, 0.f);
    r[i] = b;
}

// ---------------------------------------------------------------------------
// Mean-pool graph 0 (batch sorted -> prefix), fc head, softmax, write probs[0]
// ---------------------------------------------------------------------------
__global__ void __launch_bounds__(256) pool_head(
    const float* __restrict__ h, const int* __restrict__ batch,
    const float* __restrict__ Wfc, const float* __restrict__ bfc,
    float* __restrict__ out, int N)
{
    __shared__ float ssum[4][HID];
    __shared__ float scnt[4];
    __shared__ float smean[HID];
    __shared__ float slog[TYPE_NUM];

    int tid = threadIdx.x;
    int g = tid >> 6;     // 0..3
    int d = tid & 63;

    float acc = 0.f;
    int cnt = 0;
    for (int i = g; i < N; i += 4) {
        if (batch[i] != 0) break;     // sorted: graph 0 is a prefix
        acc += h[(size_t)i * HID + d];
        cnt++;
    }
    ssum[g][d] = acc;
    if (d == 0) scnt[g] = (float)cnt;
    __syncthreads();

    if (tid < HID) {
        float m = ssum[0][tid] + ssum[1][tid] + ssum[2][tid] + ssum[3][tid];
        float c = scnt[0] + scnt[1] + scnt[2] + scnt[3];
        smean[tid] = m / fmaxf(c, 1.f);
    }
    __syncthreads();

    if (tid < TYPE_NUM) {
        float l = bfc[tid];
        #pragma unroll
        for (int k = 0; k < HID; k++) l += smean[k] * Wfc[k * TYPE_NUM + tid];
        slog[tid] = l;
    }
    __syncthreads();

    if (tid == 0) {
        float mx = slog[0];
        #pragma unroll
        for (int j = 1; j < TYPE_NUM; j++) mx = fmaxf(mx, slog[j]);
        float s = 0.f;
        float ex[TYPE_NUM];
        #pragma unroll
        for (int j = 0; j < TYPE_NUM; j++) { ex[j] = __expf(slog[j] - mx); s += ex[j]; }
        float inv = 1.f / s;
        #pragma unroll
        for (int j = 0; j < TYPE_NUM; j++) out[j] = ex[j] * inv;
    }
}

// ---------------------------------------------------------------------------
extern "C" void kernel_launch(void* const* d_in, const int* in_sizes, int n_in,
                              void* d_out, int out_size)
{
    const float* x      = (const float*)d_in[0];
    const int*   ei     = (const int*)  d_in[1];   // int32 (JAX default x64 off)
    const int*   batch  = (const int*)  d_in[2];   // int32
    const float* Wrel1  = (const float*)d_in[3];
    const float* Wroot1 = (const float*)d_in[4];
    const float* Wrel2  = (const float*)d_in[5];
    const float* Wroot2 = (const float*)d_in[6];
    const float* Wrel3  = (const float*)d_in[7];
    const float* Wroot3 = (const float*)d_in[8];
    const float* Wfc    = (const float*)d_in[9];
    const float* bfc    = (const float*)d_in[10];
    float* out = (float*)d_out;

    float4 *py4, *prA4, *prB4, *pagg4;
    cudaGetSymbolAddress((void**)&py4,   g_y);
    cudaGetSymbolAddress((void**)&prA4,  g_rA);
    cudaGetSymbolAddress((void**)&prB4,  g_rB);
    cudaGetSymbolAddress((void**)&pagg4, g_agg);
    float* py   = (float*)py4;
    float* prA  = (float*)prA4;
    float* prB  = (float*)prB4;
    float* pagg = (float*)pagg4;

    const int N = N_NODES, E = N_EDGES;
    const int gemm_blocks = (N + 63) / 64;
    const int scat_blocks = (E * 16 + 255) / 256;
    const int n4 = N * HID / 4;
    const int relu_blocks = (n4 + 255) / 256;

    // Layer 1 (K=128): in = x, output -> rA
    dual_gemm<FEAT><<<gemm_blocks, 256>>>(x, Wrel1, Wroot1, py, prA, pagg, N);
    scatter_edges<<<scat_blocks, 256>>>(py4, ei, pagg4, E);
    relu_add<<<relu_blocks, 256>>>(pagg4, prA4, n4);

    // Layer 2 (K=64): in = rA, output -> rB
    dual_gemm<HID><<<gemm_blocks, 256>>>(prA, Wrel2, Wroot2, py, prB, pagg, N);
    scatter_edges<<<scat_blocks, 256>>>(py4, ei, pagg4, E);
    relu_add<<<relu_blocks, 256>>>(pagg4, prB4, n4);

    // Layer 3 (K=64): in = rB, output -> rA
    dual_gemm<HID><<<gemm_blocks, 256>>>(prB, Wrel3, Wroot3, py, prA, pagg, N);
    scatter_edges<<<scat_blocks, 256>>>(py4, ei, pagg4, E);
    relu_add<<<relu_blocks, 256>>>(pagg4, prA4, n4);

    // Head
    pool_head<<<1, 256>>>(prA, batch, Wfc, bfc, out, N);
}

// round 4
// speedup vs baseline: 1.1480x; 1.1480x over previous
#include <cuda_runtime.h>
#include <cuda_bf16.h>
#include <math.h>

#define N_NODES 50000
#define N_EDGES 800000
#define FEAT    128
#define HID     64
#define TYPE_NUM 10

// ---------------- scratch buffers (float4-typed => 16B alignment) -----------
__device__ float4 g_y   [N_NODES * HID / 4];   // rel-transformed features
__device__ float4 g_rA  [N_NODES * HID / 4];   // root part / layer output (ping)
__device__ float4 g_rB  [N_NODES * HID / 4];   // root part / layer output (pong)
__device__ float4 g_agg [N_NODES * HID / 4];   // aggregation target A
__device__ float4 g_agg2[N_NODES * HID / 4];   // aggregation target B
__device__ unsigned char g_flag[N_NODES];      // layer-2 active-node flags

// ---------------------------------------------------------------------------
// Dual GEMM: y = in @ Wrel, r = in @ Wroot   (in: [N,K], W: [K,64])
// FUSED: input is relu(inA + inB) computed on the fly (layer-2 input fusion).
// Also zeroes the agg rows of this tile and (optionally) the flag bytes.
// ---------------------------------------------------------------------------
template<int K, bool FUSED>
__global__ void __launch_bounds__(256) dual_gemm(
    const float* __restrict__ inA, const float* __restrict__ inB,
    const float* __restrict__ Wr,  const float* __restrict__ Wo,
    float* __restrict__ y, float* __restrict__ r,
    float* __restrict__ aggz, unsigned char* flagz, int N)
{
    __shared__ float sIn[32][68];
    __shared__ float sWr[32][64];
    __shared__ float sWo[32][64];

    const int tid  = threadIdx.x;
    const int col  = tid & 63;
    const int rg   = tid >> 6;
    const int row0 = blockIdx.x * 64;

    // zero agg rows of this tile (for the upcoming scatter)
    {
        int limit = (N - row0) * HID;
        if (limit > 64 * HID) limit = 64 * HID;
        int base = row0 * HID;
        for (int i = tid; i < limit; i += 256) aggz[base + i] = 0.f;
    }
    if (flagz && tid < 64 && row0 + tid < N) flagz[row0 + tid] = 0;

    float accY[16], accR[16];
    #pragma unroll
    for (int j = 0; j < 16; j++) { accY[j] = 0.f; accR[j] = 0.f; }

    for (int kc = 0; kc < K; kc += 32) {
        __syncthreads();
        #pragma unroll
        for (int e = 0; e < 8; e++) {
            int linear = tid + e * 256;
            int rl = linear >> 5;
            int kl = linear & 31;
            int grow = row0 + rl;
            float v = 0.f;
            if (grow < N) {
                size_t idx = (size_t)grow * K + kc + kl;
                if (FUSED) v = fmaxf(inA[idx] + inB[idx], 0.f);
                else       v = inA[idx];
            }
            sIn[kl][rl] = v;
        }
        #pragma unroll
        for (int e = 0; e < 8; e++) {
            int linear = tid + e * 256;
            int kk = linear >> 6;
            int cc = linear & 63;
            sWr[kk][cc] = Wr[(size_t)(kc + kk) * HID + cc];
            sWo[kk][cc] = Wo[(size_t)(kc + kk) * HID + cc];
        }
        __syncthreads();

        #pragma unroll
        for (int k = 0; k < 32; k++) {
            float wr = sWr[k][col];
            float wo = sWo[k][col];
            const float4* rowp = (const float4*)(&sIn[k][rg * 16]);
            #pragma unroll
            for (int q = 0; q < 4; q++) {
                float4 a = rowp[q];
                accY[q*4+0] += a.x * wr;  accR[q*4+0] += a.x * wo;
                accY[q*4+1] += a.y * wr;  accR[q*4+1] += a.y * wo;
                accY[q*4+2] += a.z * wr;  accR[q*4+2] += a.z * wo;
                accY[q*4+3] += a.w * wr;  accR[q*4+3] += a.w * wo;
            }
        }
    }

    #pragma unroll
    for (int j = 0; j < 16; j++) {
        int grow = row0 + rg * 16 + j;
        if (grow < N) {
            y[(size_t)grow * HID + col] = accY[j];
            r[(size_t)grow * HID + col] = accR[j];
        }
    }
}

// ---------------------------------------------------------------------------
// Edge scatter variants: agg[dst] += y[src]   (float4 atomics, 16 thr/edge)
// ---------------------------------------------------------------------------
__global__ void __launch_bounds__(256) scatter_full(
    const float4* __restrict__ y, const int* __restrict__ ei,
    float4* __restrict__ agg, int E)
{
    int t = blockIdx.x * blockDim.x + threadIdx.x;
    int e = t >> 4;
    if (e >= E) return;
    int lane = t & 15;
    int s = ei[e];
    int d = ei[E + e];
    float4 v = y[(size_t)s * (HID / 4) + lane];
    atomicAdd(&agg[(size_t)d * (HID / 4) + lane], v);
}

__global__ void __launch_bounds__(256) scatter_flag(
    const float4* __restrict__ y, const int* __restrict__ ei,
    float4* __restrict__ agg, const unsigned char* __restrict__ flag, int E)
{
    int t = blockIdx.x * blockDim.x + threadIdx.x;
    int e = t >> 4;
    if (e >= E) return;
    int d = ei[E + e];
    if (!flag[d]) return;
    int lane = t & 15;
    int s = ei[e];
    float4 v = y[(size_t)s * (HID / 4) + lane];
    atomicAdd(&agg[(size_t)d * (HID / 4) + lane], v);
}

__global__ void __launch_bounds__(256) scatter_b0(
    const float4* __restrict__ y, const int* __restrict__ ei,
    float4* __restrict__ agg, const int* __restrict__ batch, int E)
{
    int t = blockIdx.x * blockDim.x + threadIdx.x;
    int e = t >> 4;
    if (e >= E) return;
    int d = ei[E + e];
    if (batch[d] != 0) return;
    int lane = t & 15;
    int s = ei[e];
    float4 v = y[(size_t)s * (HID / 4) + lane];
    atomicAdd(&agg[(size_t)d * (HID / 4) + lane], v);
}

// ---------------------------------------------------------------------------
// Build layer-2 active flags: nodes in graph 0, plus sources of edges whose
// destination is in graph 0.
// ---------------------------------------------------------------------------
__global__ void __launch_bounds__(256) build_flags(
    const int* __restrict__ ei, const int* __restrict__ batch,
    unsigned char* __restrict__ flag, int E, int N)
{
    int t = blockIdx.x * blockDim.x + threadIdx.x;
    if (t < N && batch[t] == 0) flag[t] = 1;
    if (t < E) {
        int d = ei[E + t];
        if (batch[d] == 0) flag[ei[t]] = 1;
    }
}

// ---------------------------------------------------------------------------
// h = relu(agg + r) in place into r; also zero aggz (recycled for layer 3)
// ---------------------------------------------------------------------------
__global__ void __launch_bounds__(256) relu_zero(
    const float4* __restrict__ agg, float4* __restrict__ r,
    float4* __restrict__ aggz, int n4)
{
    int i = blockIdx.x * blockDim.x + threadIdx.x;
    if (i >= n4) return;
    float4 a = agg[i];
    float4 b = r[i];
    b.x = fmaxf(a.x + b.x, 0.f);
    b.y = fmaxf(a.y + b.y, 0.f);
    b.z = fmaxf(a.z + b.z, 0.f);
    b.w = fmaxf(a.w + b.w, 0.f);
    r[i] = b;
    aggz[i] = make_float4(0.f, 0.f, 0.f, 0.f).x == 0.f ? make_float4(0.f,0.f,0.f,0.f) : make_float4(0.f,0.f,0.f,0.f);
}

// ---------------------------------------------------------------------------
// Layer-3 GEMM restricted to the graph-0 prefix (batch sorted):
// h3 = relu(agg @ Wrel + h2 @ Wroot). Blocks whose tile starts past the
// prefix exit immediately.
// ---------------------------------------------------------------------------
__global__ void __launch_bounds__(256) gemm3_prefix(
    const float* __restrict__ agg, const float* __restrict__ h2,
    const float* __restrict__ Wr,  const float* __restrict__ Wo,
    const int* __restrict__ batch, float* __restrict__ h3, int N)
{
    const int row0 = blockIdx.x * 64;
    if (batch[row0] != 0) return;     // sorted => whole tile outside prefix

    __shared__ float sA[32][68];
    __shared__ float sB[32][68];
    __shared__ float sWr[32][64];
    __shared__ float sWo[32][64];

    const int tid = threadIdx.x;
    const int col = tid & 63;
    const int rg  = tid >> 6;

    float acc[16];
    #pragma unroll
    for (int j = 0; j < 16; j++) acc[j] = 0.f;

    for (int kc = 0; kc < HID; kc += 32) {
        __syncthreads();
        #pragma unroll
        for (int e = 0; e < 8; e++) {
            int linear = tid + e * 256;
            int rl = linear >> 5;
            int kl = linear & 31;
            int grow = row0 + rl;
            float va = 0.f, vb = 0.f;
            if (grow < N) {
                size_t idx = (size_t)grow * HID + kc + kl;
                va = agg[idx];
                vb = h2[idx];
            }
            sA[kl][rl] = va;
            sB[kl][rl] = vb;
        }
        #pragma unroll
        for (int e = 0; e < 8; e++) {
            int linear = tid + e * 256;
            int kk = linear >> 6;
            int cc = linear & 63;
            sWr[kk][cc] = Wr[(size_t)(kc + kk) * HID + cc];
            sWo[kk][cc] = Wo[(size_t)(kc + kk) * HID + cc];
        }
        __syncthreads();

        #pragma unroll
        for (int k = 0; k < 32; k++) {
            float wr = sWr[k][col];
            float wo = sWo[k][col];
            const float4* ra = (const float4*)(&sA[k][rg * 16]);
            const float4* rb = (const float4*)(&sB[k][rg * 16]);
            #pragma unroll
            for (int q = 0; q < 4; q++) {
                float4 a = ra[q];
                float4 b = rb[q];
                acc[q*4+0] += a.x * wr + b.x * wo;
                acc[q*4+1] += a.y * wr + b.y * wo;
                acc[q*4+2] += a.z * wr + b.z * wo;
                acc[q*4+3] += a.w * wr + b.w * wo;
            }
        }
    }

    #pragma unroll
    for (int j = 0; j < 16; j++) {
        int grow = row0 + rg * 16 + j;
        if (grow < N) h3[(size_t)grow * HID + col] = fmaxf(acc[j], 0.f);
    }
}

// ---------------------------------------------------------------------------
// Mean-pool graph 0, fc head, softmax, write probs[0]
// ---------------------------------------------------------------------------
__global__ void __launch_bounds__(256) pool_head(
    const float* __restrict__ h, const int* __restrict__ batch,
    const float* __restrict__ Wfc, const float* __restrict__ bfc,
    float* __restrict__ out, int N)
{
    __shared__ float ssum[4][HID];
    __shared__ float scnt[4];
    __shared__ float smean[HID];
    __shared__ float slog[TYPE_NUM];

    int tid = threadIdx.x;
    int g = tid >> 6;
    int d = tid & 63;

    float acc = 0.f;
    int cnt = 0;
    for (int i = g; i < N; i += 4) {
        if (batch[i] != 0) break;
        acc += h[(size_t)i * HID + d];
        cnt++;
    }
    ssum[g][d] = acc;
    if (d == 0) scnt[g] = (float)cnt;
    __syncthreads();

    if (tid < HID) {
        float m = ssum[0][tid] + ssum[1][tid] + ssum[2][tid] + ssum[3][tid];
        float c = scnt[0] + scnt[1] + scnt[2] + scnt[3];
        smean[tid] = m / fmaxf(c, 1.f);
    }
    __syncthreads();

    if (tid < TYPE_NUM) {
        float l = bfc[tid];
        #pragma unroll
        for (int k = 0; k < HID; k++) l += smean[k] * Wfc[k * TYPE_NUM + tid];
        slog[tid] = l;
    }
    __syncthreads();

    if (tid == 0) {
        float mx = slog[0];
        #pragma unroll
        for (int j = 1; j < TYPE_NUM; j++) mx = fmaxf(mx, slog[j]);
        float s = 0.f;
        float ex[TYPE_NUM];
        #pragma unroll
        for (int j = 0; j < TYPE_NUM; j++) { ex[j] = __expf(slog[j] - mx); s += ex[j]; }
        float inv = 1.f / s;
        #pragma unroll
        for (int j = 0; j < TYPE_NUM; j++) out[j] = ex[j] * inv;
    }
}

// ---------------------------------------------------------------------------
extern "C" void kernel_launch(void* const* d_in, const int* in_sizes, int n_in,
                              void* d_out, int out_size)
{
    const float* x      = (const float*)d_in[0];
    const int*   ei     = (const int*)  d_in[1];   // int32 (JAX x64 off)
    const int*   batch  = (const int*)  d_in[2];   // int32
    const float* Wrel1  = (const float*)d_in[3];
    const float* Wroot1 = (const float*)d_in[4];
    const float* Wrel2  = (const float*)d_in[5];
    const float* Wroot2 = (const float*)d_in[6];
    const float* Wrel3  = (const float*)d_in[7];
    const float* Wroot3 = (const float*)d_in[8];
    const float* Wfc    = (const float*)d_in[9];
    const float* bfc    = (const float*)d_in[10];
    float* out = (float*)d_out;

    float4 *py4, *prA4, *prB4, *pagg4, *pagg24;
    unsigned char* pflag;
    cudaGetSymbolAddress((void**)&py4,    g_y);
    cudaGetSymbolAddress((void**)&prA4,   g_rA);
    cudaGetSymbolAddress((void**)&prB4,   g_rB);
    cudaGetSymbolAddress((void**)&pagg4,  g_agg);
    cudaGetSymbolAddress((void**)&pagg24, g_agg2);
    cudaGetSymbolAddress((void**)&pflag,  g_flag);
    float* py    = (float*)py4;
    float* prA   = (float*)prA4;
    float* prB   = (float*)prB4;
    float* pagg  = (float*)pagg4;
    float* pagg2 = (float*)pagg24;

    const int N = N_NODES, E = N_EDGES;
    const int gemm_blocks = (N + 63) / 64;
    const int scat_blocks = (E * 16 + 255) / 256;
    const int flag_blocks = (E + 255) / 256;
    const int n4 = N * HID / 4;
    const int relu_blocks = (n4 + 255) / 256;

    // Layer 1 (K=128): y1,r1 <- x; zero agg; zero flags
    dual_gemm<FEAT, false><<<gemm_blocks, 256>>>(x, nullptr, Wrel1, Wroot1,
                                                 py, prA, pagg, pflag, N);
    scatter_full<<<scat_blocks, 256>>>(py4, ei, pagg4, E);
    build_flags<<<flag_blocks, 256>>>(ei, batch, pflag, E, N);

    // Layer 2 (K=64): input = relu(agg + r1) fused; zero agg2
    dual_gemm<HID, true><<<gemm_blocks, 256>>>(pagg, prA, Wrel2, Wroot2,
                                               py, prB, pagg2, nullptr, N);
    scatter_flag<<<scat_blocks, 256>>>(py4, ei, pagg24, pflag, E);

    // h2 = relu(agg2 + r2) -> rB ; zero agg for layer 3
    relu_zero<<<relu_blocks, 256>>>(pagg24, prB4, pagg4, n4);

    // Layer 3 restricted to graph 0: agg <- sum h2[src] over edges into graph0
    scatter_b0<<<scat_blocks, 256>>>(prB4, ei, pagg4, batch, E);
    gemm3_prefix<<<gemm_blocks, 256>>>(pagg, prB, Wrel3, Wroot3, batch, prA, N);

    // Head
    pool_head<<<1, 256>>>(prA, batch, Wfc, bfc, out, N);
}

// round 5
// speedup vs baseline: 1.1527x; 1.0041x over previous
#include <cuda_runtime.h>
#include <cuda_bf16.h>
#include <math.h>

#define N_NODES 50000
#define N_EDGES 800000
#define FEAT    128
#define HID     64
#define TYPE_NUM 10

// ---------------- scratch buffers (float4-typed => 16B alignment) -----------
__device__ float4 g_y   [N_NODES * HID / 4];
__device__ float4 g_rA  [N_NODES * HID / 4];
__device__ float4 g_rB  [N_NODES * HID / 4];
__device__ float4 g_agg [N_NODES * HID / 4];
__device__ float4 g_agg2[N_NODES * HID / 4];
__device__ unsigned char g_flag[N_NODES];
__device__ int g_cnt2, g_cnt3;
__device__ int g_e2s[N_EDGES], g_e2d[N_EDGES];
__device__ int g_e3s[N_EDGES], g_e3d[N_EDGES];

// packed f32x2 helpers --------------------------------------------------------
#define FMA2(acc, a, b) \
    asm("fma.rn.f32x2 %0, %1, %2, %3;" : "=l"(acc) : "l"(a), "l"(b), "l"(acc))

__device__ __forceinline__ unsigned long long bcast2(float v) {
    unsigned long long r;
    unsigned u = __float_as_uint(v);
    asm("mov.b64 %0, {%1, %1};" : "=l"(r) : "r"(u));
    return r;
}
__device__ __forceinline__ float f2_lo(unsigned long long v) {
    return __uint_as_float((unsigned)v);
}
__device__ __forceinline__ float f2_hi(unsigned long long v) {
    return __uint_as_float((unsigned)(v >> 32));
}

// ---------------------------------------------------------------------------
// Dual GEMM with packed f32x2 FMA: y = in @ Wrel, r = in @ Wroot
// FUSED: input = relu(inA + inB) on the fly. Zeroes agg tile (+flags).
// ---------------------------------------------------------------------------
template<int K, bool FUSED>
__global__ void __launch_bounds__(256) dual_gemm(
    const float* __restrict__ inA, const float* __restrict__ inB,
    const float* __restrict__ Wr,  const float* __restrict__ Wo,
    float* __restrict__ y, float* __restrict__ r,
    float* __restrict__ aggz, unsigned char* flagz, int N)
{
    __shared__ float sIn[32][68];   // row stride 272B = 17*16B -> 16B-aligned rows
    __shared__ float sWr[32][64];
    __shared__ float sWo[32][64];

    const int tid  = threadIdx.x;
    const int col  = tid & 63;
    const int rg   = tid >> 6;
    const int row0 = blockIdx.x * 64;

    {
        int limit = (N - row0) * HID;
        if (limit > 64 * HID) limit = 64 * HID;
        int base = row0 * HID;
        for (int i = tid; i < limit; i += 256) aggz[base + i] = 0.f;
    }
    if (flagz && tid < 64 && row0 + tid < N) flagz[row0 + tid] = 0;

    unsigned long long accY[8], accR[8];
    #pragma unroll
    for (int j = 0; j < 8; j++) { accY[j] = 0ull; accR[j] = 0ull; }

    for (int kc = 0; kc < K; kc += 32) {
        __syncthreads();
        #pragma unroll
        for (int e = 0; e < 8; e++) {
            int linear = tid + e * 256;
            int rl = linear >> 5;
            int kl = linear & 31;
            int grow = row0 + rl;
            float v = 0.f;
            if (grow < N) {
                size_t idx = (size_t)grow * K + kc + kl;
                if (FUSED) v = fmaxf(inA[idx] + inB[idx], 0.f);
                else       v = inA[idx];
            }
            sIn[kl][rl] = v;
        }
        #pragma unroll
        for (int e = 0; e < 8; e++) {
            int linear = tid + e * 256;
            int kk = linear >> 6;
            int cc = linear & 63;
            sWr[kk][cc] = Wr[(size_t)(kc + kk) * HID + cc];
            sWo[kk][cc] = Wo[(size_t)(kc + kk) * HID + cc];
        }
        __syncthreads();

        #pragma unroll
        for (int k = 0; k < 32; k++) {
            unsigned long long wr2 = bcast2(sWr[k][col]);
            unsigned long long wo2 = bcast2(sWo[k][col]);
            const ulonglong2* rowp = (const ulonglong2*)(&sIn[k][rg * 16]);
            #pragma unroll
            for (int q = 0; q < 4; q++) {
                ulonglong2 a = rowp[q];
                FMA2(accY[q*2+0], a.x, wr2);
                FMA2(accY[q*2+1], a.y, wr2);
                FMA2(accR[q*2+0], a.x, wo2);
                FMA2(accR[q*2+1], a.y, wo2);
            }
        }
    }

    #pragma unroll
    for (int j = 0; j < 16; j++) {
        int grow = row0 + rg * 16 + j;
        if (grow < N) {
            float vy = (j & 1) ? f2_hi(accY[j >> 1]) : f2_lo(accY[j >> 1]);
            float vr = (j & 1) ? f2_hi(accR[j >> 1]) : f2_lo(accR[j >> 1]);
            y[(size_t)grow * HID + col] = vy;
            r[(size_t)grow * HID + col] = vr;
        }
    }
}

// ---------------------------------------------------------------------------
// Full edge scatter (layer 1): agg[dst] += y[src]
// ---------------------------------------------------------------------------
__global__ void __launch_bounds__(256) scatter_full(
    const float4* __restrict__ y, const int* __restrict__ ei,
    float4* __restrict__ agg, int E)
{
    int t = blockIdx.x * blockDim.x + threadIdx.x;
    int e = t >> 4;
    if (e >= E) return;
    int lane = t & 15;
    int s = ei[e];
    int d = ei[E + e];
    float4 v = y[(size_t)s * (HID / 4) + lane];
    atomicAdd(&agg[(size_t)d * (HID / 4) + lane], v);
}

// ---------------------------------------------------------------------------
// Flags: graph-0 nodes + sources of edges into graph 0. Also zero counters.
// ---------------------------------------------------------------------------
__global__ void __launch_bounds__(256) build_flags(
    const int* __restrict__ ei, const int* __restrict__ batch,
    unsigned char* __restrict__ flag, int E, int N)
{
    int t = blockIdx.x * blockDim.x + threadIdx.x;
    if (t == 0) { g_cnt2 = 0; g_cnt3 = 0; }
    if (t < N && batch[t] == 0) flag[t] = 1;
    if (t < E) {
        int d = ei[E + t];
        if (batch[d] == 0) flag[ei[t]] = 1;
    }
}

// ---------------------------------------------------------------------------
// Compact edge lists: e2 = edges into flagged nodes, e3 = edges into graph 0
// ---------------------------------------------------------------------------
__global__ void __launch_bounds__(256) compact_edges(
    const int* __restrict__ ei, const int* __restrict__ batch,
    const unsigned char* __restrict__ flag, int E)
{
    int t = blockIdx.x * blockDim.x + threadIdx.x;
    if (t >= E) return;
    int s = ei[t];
    int d = ei[E + t];
    if (flag[d]) {
        int i = atomicAdd(&g_cnt2, 1);
        g_e2s[i] = s; g_e2d[i] = d;
    }
    if (batch[d] == 0) {
        int j = atomicAdd(&g_cnt3, 1);
        g_e3s[j] = s; g_e3d[j] = d;
    }
}

// ---------------------------------------------------------------------------
// Compacted scatters
// ---------------------------------------------------------------------------
__global__ void __launch_bounds__(256) scatter_c2(
    const float4* __restrict__ y, float4* __restrict__ agg)
{
    int cnt = g_cnt2;
    int t = blockIdx.x * blockDim.x + threadIdx.x;
    int e = t >> 4;
    if (e >= cnt) return;
    int lane = t & 15;
    int s = g_e2s[e];
    int d = g_e2d[e];
    float4 v = y[(size_t)s * (HID / 4) + lane];
    atomicAdd(&agg[(size_t)d * (HID / 4) + lane], v);
}

__global__ void __launch_bounds__(256) scatter_c3(
    const float4* __restrict__ y, float4* __restrict__ agg)
{
    int cnt = g_cnt3;
    int t = blockIdx.x * blockDim.x + threadIdx.x;
    int e = t >> 4;
    if (e >= cnt) return;
    int lane = t & 15;
    int s = g_e3s[e];
    int d = g_e3d[e];
    float4 v = y[(size_t)s * (HID / 4) + lane];
    atomicAdd(&agg[(size_t)d * (HID / 4) + lane], v);
}

// ---------------------------------------------------------------------------
// h = relu(agg + r) in place into r; zero aggz rows only where batch==0
// ---------------------------------------------------------------------------
__global__ void __launch_bounds__(256) relu_zero(
    const float4* __restrict__ agg, float4* __restrict__ r,
    float4* __restrict__ aggz, const int* __restrict__ batch, int n4)
{
    int i = blockIdx.x * blockDim.x + threadIdx.x;
    if (i >= n4) return;
    float4 a = agg[i];
    float4 b = r[i];
    b.x = fmaxf(a.x + b.x, 0.f);
    b.y = fmaxf(a.y + b.y, 0.f);
    b.z = fmaxf(a.z + b.z, 0.f);
    b.w = fmaxf(a.w + b.w, 0.f);
    r[i] = b;
    if (batch[i >> 4] == 0) aggz[i] = make_float4(0.f, 0.f, 0.f, 0.f);
}

// ---------------------------------------------------------------------------
// Layer-3 GEMM on the graph-0 prefix only
// ---------------------------------------------------------------------------
__global__ void __launch_bounds__(256) gemm3_prefix(
    const float* __restrict__ agg, const float* __restrict__ h2,
    const float* __restrict__ Wr,  const float* __restrict__ Wo,
    const int* __restrict__ batch, float* __restrict__ h3, int N)
{
    const int row0 = blockIdx.x * 64;
    if (batch[row0] != 0) return;

    __shared__ float sA[32][68];
    __shared__ float sB[32][68];
    __shared__ float sWr[32][64];
    __shared__ float sWo[32][64];

    const int tid = threadIdx.x;
    const int col = tid & 63;
    const int rg  = tid >> 6;

    unsigned long long acc[8];
    #pragma unroll
    for (int j = 0; j < 8; j++) acc[j] = 0ull;

    for (int kc = 0; kc < HID; kc += 32) {
        __syncthreads();
        #pragma unroll
        for (int e = 0; e < 8; e++) {
            int linear = tid + e * 256;
            int rl = linear >> 5;
            int kl = linear & 31;
            int grow = row0 + rl;
            float va = 0.f, vb = 0.f;
            if (grow < N) {
                size_t idx = (size_t)grow * HID + kc + kl;
                va = agg[idx];
                vb = h2[idx];
            }
            sA[kl][rl] = va;
            sB[kl][rl] = vb;
        }
        #pragma unroll
        for (int e = 0; e < 8; e++) {
            int linear = tid + e * 256;
            int kk = linear >> 6;
            int cc = linear & 63;
            sWr[kk][cc] = Wr[(size_t)(kc + kk) * HID + cc];
            sWo[kk][cc] = Wo[(size_t)(kc + kk) * HID + cc];
        }
        __syncthreads();

        #pragma unroll
        for (int k = 0; k < 32; k++) {
            unsigned long long wr2 = bcast2(sWr[k][col]);
            unsigned long long wo2 = bcast2(sWo[k][col]);
            const ulonglong2* ra = (const ulonglong2*)(&sA[k][rg * 16]);
            const ulonglong2* rb = (const ulonglong2*)(&sB[k][rg * 16]);
            #pragma unroll
            for (int q = 0; q < 4; q++) {
                ulonglong2 a = ra[q];
                ulonglong2 b = rb[q];
                FMA2(acc[q*2+0], a.x, wr2);
                FMA2(acc[q*2+1], a.y, wr2);
                FMA2(acc[q*2+0], b.x, wo2);
                FMA2(acc[q*2+1], b.y, wo2);
            }
        }
    }

    #pragma unroll
    for (int j = 0; j < 16; j++) {
        int grow = row0 + rg * 16 + j;
        if (grow < N) {
            float v = (j & 1) ? f2_hi(acc[j >> 1]) : f2_lo(acc[j >> 1]);
            h3[(size_t)grow * HID + col] = fmaxf(v, 0.f);
        }
    }
}

// ---------------------------------------------------------------------------
// Mean-pool graph 0, fc head, softmax
// ---------------------------------------------------------------------------
__global__ void __launch_bounds__(256) pool_head(
    const float* __restrict__ h, const int* __restrict__ batch,
    const float* __restrict__ Wfc, const float* __restrict__ bfc,
    float* __restrict__ out, int N)
{
    __shared__ float ssum[4][HID];
    __shared__ float scnt[4];
    __shared__ float smean[HID];
    __shared__ float slog[TYPE_NUM];

    int tid = threadIdx.x;
    int g = tid >> 6;
    int d = tid & 63;

    float acc = 0.f;
    int cnt = 0;
    for (int i = g; i < N; i += 4) {
        if (batch[i] != 0) break;
        acc += h[(size_t)i * HID + d];
        cnt++;
    }
    ssum[g][d] = acc;
    if (d == 0) scnt[g] = (float)cnt;
    __syncthreads();

    if (tid < HID) {
        float m = ssum[0][tid] + ssum[1][tid] + ssum[2][tid] + ssum[3][tid];
        float c = scnt[0] + scnt[1] + scnt[2] + scnt[3];
        smean[tid] = m / fmaxf(c, 1.f);
    }
    __syncthreads();

    if (tid < TYPE_NUM) {
        float l = bfc[tid];
        #pragma unroll
        for (int k = 0; k < HID; k++) l += smean[k] * Wfc[k * TYPE_NUM + tid];
        slog[tid] = l;
    }
    __syncthreads();

    if (tid == 0) {
        float mx = slog[0];
        #pragma unroll
        for (int j = 1; j < TYPE_NUM; j++) mx = fmaxf(mx, slog[j]);
        float s = 0.f;
        float ex[TYPE_NUM];
        #pragma unroll
        for (int j = 0; j < TYPE_NUM; j++) { ex[j] = __expf(slog[j] - mx); s += ex[j]; }
        float inv = 1.f / s;
        #pragma unroll
        for (int j = 0; j < TYPE_NUM; j++) out[j] = ex[j] * inv;
    }
}

// ---------------------------------------------------------------------------
extern "C" void kernel_launch(void* const* d_in, const int* in_sizes, int n_in,
                              void* d_out, int out_size)
{
    const float* x      = (const float*)d_in[0];
    const int*   ei     = (const int*)  d_in[1];
    const int*   batch  = (const int*)  d_in[2];
    const float* Wrel1  = (const float*)d_in[3];
    const float* Wroot1 = (const float*)d_in[4];
    const float* Wrel2  = (const float*)d_in[5];
    const float* Wroot2 = (const float*)d_in[6];
    const float* Wrel3  = (const float*)d_in[7];
    const float* Wroot3 = (const float*)d_in[8];
    const float* Wfc    = (const float*)d_in[9];
    const float* bfc    = (const float*)d_in[10];
    float* out = (float*)d_out;

    float4 *py4, *prA4, *prB4, *pagg4, *pagg24;
    unsigned char* pflag;
    cudaGetSymbolAddress((void**)&py4,    g_y);
    cudaGetSymbolAddress((void**)&prA4,   g_rA);
    cudaGetSymbolAddress((void**)&prB4,   g_rB);
    cudaGetSymbolAddress((void**)&pagg4,  g_agg);
    cudaGetSymbolAddress((void**)&pagg24, g_agg2);
    cudaGetSymbolAddress((void**)&pflag,  g_flag);
    float* py    = (float*)py4;
    float* prA   = (float*)prA4;
    float* prB   = (float*)prB4;
    float* pagg  = (float*)pagg4;
    float* pagg2 = (float*)pagg24;

    const int N = N_NODES, E = N_EDGES;
    const int gemm_blocks = (N + 63) / 64;
    const int scat_blocks = (E * 16 + 255) / 256;
    const int flag_blocks = (E + 255) / 256;
    const int n4 = N * HID / 4;
    const int relu_blocks = (n4 + 255) / 256;

    // Layer 1 (K=128): y1,r1 <- x; zero agg; zero flags
    dual_gemm<FEAT, false><<<gemm_blocks, 256>>>(x, nullptr, Wrel1, Wroot1,
                                                 py, prA, pagg, pflag, N);
    scatter_full<<<scat_blocks, 256>>>(py4, ei, pagg4, E);
    build_flags<<<flag_blocks, 256>>>(ei, batch, pflag, E, N);
    compact_edges<<<flag_blocks, 256>>>(ei, batch, pflag, E);

    // Layer 2 (K=64): input = relu(agg + r1) fused; zero agg2
    dual_gemm<HID, true><<<gemm_blocks, 256>>>(pagg, prA, Wrel2, Wroot2,
                                               py, prB, pagg2, nullptr, N);
    scatter_c2<<<scat_blocks, 256>>>(py4, pagg24);

    // h2 = relu(agg2 + r2) -> rB ; zero agg prefix rows for layer 3
    relu_zero<<<relu_blocks, 256>>>(pagg24, prB4, pagg4, batch, n4);

    // Layer 3 restricted to graph 0
    scatter_c3<<<scat_blocks, 256>>>(prB4, pagg4);
    gemm3_prefix<<<gemm_blocks, 256>>>(pagg, prB, Wrel3, Wroot3, batch, prA, N);

    // Head
    pool_head<<<1, 256>>>(prA, batch, Wfc, bfc, out, N);
}

// round 7
// speedup vs baseline: 1.3699x; 1.1884x over previous
#include <cuda_runtime.h>
#include <cuda_bf16.h>
#include <math.h>

#define N_NODES 50000
#define N_EDGES 800000
#define FEAT    128
#define HID     64
#define TYPE_NUM 10

// ---------------- scratch buffers (float4-typed => 16B alignment) -----------
__device__ float4 g_y [N_NODES * HID / 4];   // transformed features / layer-3 agg
__device__ float4 g_rA[N_NODES * HID / 4];   // root part / h (ping)
__device__ float4 g_rB[N_NODES * HID / 4];   // root part / h (pong)
__device__ unsigned char g_flag[N_NODES];    // layer-2 active-node flags
__device__ int g_deg   [N_NODES];
__device__ int g_rowptr[N_NODES];
__device__ int g_cursor[N_NODES];
__device__ int g_csr   [N_EDGES];            // src node per CSR slot

// packed f32x2 helpers --------------------------------------------------------
#define FMA2(acc, a, b) \
    asm("fma.rn.f32x2 %0, %1, %2, %3;" : "=l"(acc) : "l"(a), "l"(b), "l"(acc))

__device__ __forceinline__ unsigned long long bcast2(float v) {
    unsigned long long r;
    unsigned u = __float_as_uint(v);
    asm("mov.b64 %0, {%1, %1};" : "=l"(r) : "r"(u));
    return r;
}
__device__ __forceinline__ float f2_lo(unsigned long long v) {
    return __uint_as_float((unsigned)v);
}
__device__ __forceinline__ float f2_hi(unsigned long long v) {
    return __uint_as_float((unsigned)(v >> 32));
}

// ---------------------------------------------------------------------------
// CSR build
// ---------------------------------------------------------------------------
__global__ void __launch_bounds__(256) node_init(
    const int* __restrict__ batch, int* __restrict__ deg,
    unsigned char* __restrict__ flag, int N)
{
    int t = blockIdx.x * 256 + threadIdx.x;
    if (t >= N) return;
    deg[t] = 0;
    flag[t] = (batch[t] == 0) ? 1 : 0;
}

__global__ void __launch_bounds__(256) edge_hist(
    const int* __restrict__ ei, const int* __restrict__ batch,
    int* __restrict__ deg, unsigned char* __restrict__ flag, int E)
{
    int t = blockIdx.x * 256 + threadIdx.x;
    if (t >= E) return;
    int s = ei[t];
    int d = ei[E + t];
    atomicAdd(&deg[d], 1);
    if (batch[d] == 0) flag[s] = 1;
}

// Single-block chunked exclusive scan: rowptr/cursor = exclusive prefix of deg
__global__ void __launch_bounds__(1024) scan_rowptr(
    const int* __restrict__ deg, int* __restrict__ rowptr,
    int* __restrict__ cursor, int N)
{
    __shared__ int warpsum[32];
    __shared__ int sBase;
    const int tid  = threadIdx.x;
    const int lane = tid & 31;
    const int wid  = tid >> 5;
    if (tid == 0) sBase = 0;
    __syncthreads();
    const int nchunk = (N + 1023) >> 10;
    for (int c = 0; c < nchunk; c++) {
        int idx = (c << 10) + tid;
        int v = (idx < N) ? deg[idx] : 0;
        int x = v;
        #pragma unroll
        for (int d = 1; d < 32; d <<= 1) {
            int t = __shfl_up_sync(0xffffffff, x, d);
            if (lane >= d) x += t;
        }
        if (lane == 31) warpsum[wid] = x;
        __syncthreads();
        if (wid == 0) {
            int w = warpsum[lane];
            #pragma unroll
            for (int d = 1; d < 32; d <<= 1) {
                int t = __shfl_up_sync(0xffffffff, w, d);
                if (lane >= d) w += t;
            }
            warpsum[lane] = w;
        }
        __syncthreads();
        int incl = x + (wid > 0 ? warpsum[wid - 1] : 0);
        int base = sBase;
        if (idx < N) {
            int excl = base + incl - v;
            rowptr[idx] = excl;
            cursor[idx] = excl;
        }
        __syncthreads();                    // all reads of sBase/warpsum done
        if (tid == 1023) sBase = base + incl;
        __syncthreads();
    }
}

__global__ void __launch_bounds__(256) fill_csr(
    const int* __restrict__ ei, int* __restrict__ cursor,
    int* __restrict__ csr, int E)
{
    int t = blockIdx.x * 256 + threadIdx.x;
    if (t >= E) return;
    int d = ei[E + t];
    int slot = atomicAdd(&cursor[d], 1);
    csr[slot] = ei[t];
}

// ---------------------------------------------------------------------------
// Dual GEMM with packed f32x2 FMA: y = in @ Wrel, r = in @ Wroot
// ---------------------------------------------------------------------------
template<int K>
__global__ void __launch_bounds__(256) dual_gemm(
    const float* __restrict__ in,
    const float* __restrict__ Wr,  const float* __restrict__ Wo,
    float* __restrict__ y, float* __restrict__ r, int N)
{
    __shared__ float sIn[32][68];
    __shared__ float sWr[32][64];
    __shared__ float sWo[32][64];

    const int tid  = threadIdx.x;
    const int col  = tid & 63;
    const int rg   = tid >> 6;
    const int row0 = blockIdx.x * 64;

    unsigned long long accY[8], accR[8];
    #pragma unroll
    for (int j = 0; j < 8; j++) { accY[j] = 0ull; accR[j] = 0ull; }

    for (int kc = 0; kc < K; kc += 32) {
        __syncthreads();
        #pragma unroll
        for (int e = 0; e < 8; e++) {
            int linear = tid + e * 256;
            int rl = linear >> 5;
            int kl = linear & 31;
            int grow = row0 + rl;
            sIn[kl][rl] = (grow < N) ? in[(size_t)grow * K + kc + kl] : 0.f;
        }
        #pragma unroll
        for (int e = 0; e < 8; e++) {
            int linear = tid + e * 256;
            int kk = linear >> 6;
            int cc = linear & 63;
            sWr[kk][cc] = Wr[(size_t)(kc + kk) * HID + cc];
            sWo[kk][cc] = Wo[(size_t)(kc + kk) * HID + cc];
        }
        __syncthreads();

        #pragma unroll
        for (int k = 0; k < 32; k++) {
            unsigned long long wr2 = bcast2(sWr[k][col]);
            unsigned long long wo2 = bcast2(sWo[k][col]);
            const ulonglong2* rowp = (const ulonglong2*)(&sIn[k][rg * 16]);
            #pragma unroll
            for (int q = 0; q < 4; q++) {
                ulonglong2 a = rowp[q];
                FMA2(accY[q*2+0], a.x, wr2);
                FMA2(accY[q*2+1], a.y, wr2);
                FMA2(accR[q*2+0], a.x, wo2);
                FMA2(accR[q*2+1], a.y, wo2);
            }
        }
    }

    #pragma unroll
    for (int j = 0; j < 16; j++) {
        int grow = row0 + rg * 16 + j;
        if (grow < N) {
            float vy = (j & 1) ? f2_hi(accY[j >> 1]) : f2_lo(accY[j >> 1]);
            float vr = (j & 1) ? f2_hi(accR[j >> 1]) : f2_lo(accR[j >> 1]);
            y[(size_t)grow * HID + col] = vy;
            r[(size_t)grow * HID + col] = vr;
        }
    }
}

// ---------------------------------------------------------------------------
// CSR gather aggregation. 16 threads per node, register accumulation.
// MODE 0: all nodes,      out = relu(acc + r)   (in place over r)
// MODE 1: flagged nodes,  out = relu(acc + r)
// MODE 2: graph-0 nodes,  out = acc             (raw agg for layer 3)
// ---------------------------------------------------------------------------
template<int MODE>
__global__ void __launch_bounds__(256) gather_agg(
    const float4* __restrict__ y, const int* __restrict__ rowptr,
    const int* __restrict__ deg, const int* __restrict__ csr,
    const unsigned char* __restrict__ flag, const int* __restrict__ batch,
    float4* r_io, int N)
{
    int t = blockIdx.x * 256 + threadIdx.x;
    int node = t >> 4;
    if (node >= N) return;
    if (MODE == 1 && !flag[node]) return;
    if (MODE == 2 && batch[node] != 0) return;
    int lane = t & 15;
    int start = rowptr[node];
    int end   = start + deg[node];

    float4 acc = make_float4(0.f, 0.f, 0.f, 0.f);
    int e = start;
    for (; e + 4 <= end; e += 4) {
        int s0 = csr[e], s1 = csr[e+1], s2 = csr[e+2], s3 = csr[e+3];
        float4 v0 = y[(size_t)s0 * 16 + lane];
        float4 v1 = y[(size_t)s1 * 16 + lane];
        float4 v2 = y[(size_t)s2 * 16 + lane];
        float4 v3 = y[(size_t)s3 * 16 + lane];
        acc.x += (v0.x + v1.x) + (v2.x + v3.x);
        acc.y += (v0.y + v1.y) + (v2.y + v3.y);
        acc.z += (v0.z + v1.z) + (v2.z + v3.z);
        acc.w += (v0.w + v1.w) + (v2.w + v3.w);
    }
    for (; e < end; e++) {
        float4 v = y[(size_t)csr[e] * 16 + lane];
        acc.x += v.x; acc.y += v.y; acc.z += v.z; acc.w += v.w;
    }

    size_t o = (size_t)node * 16 + lane;
    if (MODE == 2) {
        r_io[o] = acc;
    } else {
        float4 b = r_io[o];
        b.x = fmaxf(acc.x + b.x, 0.f);
        b.y = fmaxf(acc.y + b.y, 0.f);
        b.z = fmaxf(acc.z + b.z, 0.f);
        b.w = fmaxf(acc.w + b.w, 0.f);
        r_io[o] = b;
    }
}

// ---------------------------------------------------------------------------
// Layer-3 GEMM on the graph-0 prefix only: h3 = relu(agg@Wr + h2@Wo)
// ---------------------------------------------------------------------------
__global__ void __launch_bounds__(256) gemm3_prefix(
    const float* __restrict__ agg, const float* __restrict__ h2,
    const float* __restrict__ Wr,  const float* __restrict__ Wo,
    const int* __restrict__ batch, float* __restrict__ h3, int N)
{
    const int row0 = blockIdx.x * 64;
    if (batch[row0] != 0) return;

    __shared__ float sA[32][68];
    __shared__ float sB[32][68];
    __shared__ float sWr[32][64];
    __shared__ float sWo[32][64];

    const int tid = threadIdx.x;
    const int col = tid & 63;
    const int rg  = tid >> 6;

    unsigned long long acc[8];
    #pragma unroll
    for (int j = 0; j < 8; j++) acc[j] = 0ull;

    for (int kc = 0; kc < HID; kc += 32) {
        __syncthreads();
        #pragma unroll
        for (int e = 0; e < 8; e++) {
            int linear = tid + e * 256;
            int rl = linear >> 5;
            int kl = linear & 31;
            int grow = row0 + rl;
            float va = 0.f, vb = 0.f;
            if (grow < N) {
                size_t idx = (size_t)grow * HID + kc + kl;
                va = agg[idx];
                vb = h2[idx];
            }
            sA[kl][rl] = va;
            sB[kl][rl] = vb;
        }
        #pragma unroll
        for (int e = 0; e < 8; e++) {
            int linear = tid + e * 256;
            int kk = linear >> 6;
            int cc = linear & 63;
            sWr[kk][cc] = Wr[(size_t)(kc + kk) * HID + cc];
            sWo[kk][cc] = Wo[(size_t)(kc + kk) * HID + cc];
        }
        __syncthreads();

        #pragma unroll
        for (int k = 0; k < 32; k++) {
            unsigned long long wr2 = bcast2(sWr[k][col]);
            unsigned long long wo2 = bcast2(sWo[k][col]);
            const ulonglong2* ra = (const ulonglong2*)(&sA[k][rg * 16]);
            const ulonglong2* rb = (const ulonglong2*)(&sB[k][rg * 16]);
            #pragma unroll
            for (int q = 0; q < 4; q++) {
                ulonglong2 a = ra[q];
                ulonglong2 b = rb[q];
                FMA2(acc[q*2+0], a.x, wr2);
                FMA2(acc[q*2+1], a.y, wr2);
                FMA2(acc[q*2+0], b.x, wo2);
                FMA2(acc[q*2+1], b.y, wo2);
            }
        }
    }

    #pragma unroll
    for (int j = 0; j < 16; j++) {
        int grow = row0 + rg * 16 + j;
        if (grow < N) {
            float v = (j & 1) ? f2_hi(acc[j >> 1]) : f2_lo(acc[j >> 1]);
            h3[(size_t)grow * HID + col] = fmaxf(v, 0.f);
        }
    }
}

// ---------------------------------------------------------------------------
// Mean-pool graph 0, fc head, softmax
// ---------------------------------------------------------------------------
__global__ void __launch_bounds__(256) pool_head(
    const float* __restrict__ h, const int* __restrict__ batch,
    const float* __restrict__ Wfc, const float* __restrict__ bfc,
    float* __restrict__ out, int N)
{
    __shared__ float ssum[4][HID];
    __shared__ float scnt[4];
    __shared__ float smean[HID];
    __shared__ float slog[TYPE_NUM];

    int tid = threadIdx.x;
    int g = tid >> 6;
    int d = tid & 63;

    float acc = 0.f;
    int cnt = 0;
    for (int i = g; i < N; i += 4) {
        if (batch[i] != 0) break;
        acc += h[(size_t)i * HID + d];
        cnt++;
    }
    ssum[g][d] = acc;
    if (d == 0) scnt[g] = (float)cnt;
    __syncthreads();

    if (tid < HID) {
        float m = ssum[0][tid] + ssum[1][tid] + ssum[2][tid] + ssum[3][tid];
        float c = scnt[0] + scnt[1] + scnt[2] + scnt[3];
        smean[tid] = m / fmaxf(c, 1.f);
    }
    __syncthreads();

    if (tid < TYPE_NUM) {
        float l = bfc[tid];
        #pragma unroll
        for (int k = 0; k < HID; k++) l += smean[k] * Wfc[k * TYPE_NUM + tid];
        slog[tid] = l;
    }
    __syncthreads();

    if (tid == 0) {
        float mx = slog[0];
        #pragma unroll
        for (int j = 1; j < TYPE_NUM; j++) mx = fmaxf(mx, slog[j]);
        float s = 0.f;
        float ex[TYPE_NUM];
        #pragma unroll
        for (int j = 0; j < TYPE_NUM; j++) { ex[j] = __expf(slog[j] - mx); s += ex[j]; }
        float inv = 1.f / s;
        #pragma unroll
        for (int j = 0; j < TYPE_NUM; j++) out[j] = ex[j] * inv;
    }
}

// ---------------------------------------------------------------------------
extern "C" void kernel_launch(void* const* d_in, const int* in_sizes, int n_in,
                              void* d_out, int out_size)
{
    const float* x      = (const float*)d_in[0];
    const int*   ei     = (const int*)  d_in[1];
    const int*   batch  = (const int*)  d_in[2];
    const float* Wrel1  = (const float*)d_in[3];
    const float* Wroot1 = (const float*)d_in[4];
    const float* Wrel2  = (const float*)d_in[5];
    const float* Wroot2 = (const float*)d_in[6];
    const float* Wrel3  = (const float*)d_in[7];
    const float* Wroot3 = (const float*)d_in[8];
    const float* Wfc    = (const float*)d_in[9];
    const float* bfc    = (const float*)d_in[10];
    float* out = (float*)d_out;

    float4 *py4, *prA4, *prB4;
    unsigned char* pflag;
    int *pdeg, *prow, *pcur, *pcsr;
    cudaGetSymbolAddress((void**)&py4,   g_y);
    cudaGetSymbolAddress((void**)&prA4,  g_rA);
    cudaGetSymbolAddress((void**)&prB4,  g_rB);
    cudaGetSymbolAddress((void**)&pflag, g_flag);
    cudaGetSymbolAddress((void**)&pdeg,  g_deg);
    cudaGetSymbolAddress((void**)&prow,  g_rowptr);
    cudaGetSymbolAddress((void**)&pcur,  g_cursor);
    cudaGetSymbolAddress((void**)&pcsr,  g_csr);
    float* py  = (float*)py4;
    float* prA = (float*)prA4;
    float* prB = (float*)prB4;

    const int N = N_NODES, E = N_EDGES;
    const int nodeB = (N + 255) / 256;
    const int edgeB = (E + 255) / 256;
    const int gemmB = (N + 63) / 64;
    const int gathB = (N * 16 + 255) / 256;

    // CSR build + flags
    node_init  <<<nodeB, 256>>>(batch, pdeg, pflag, N);
    edge_hist  <<<edgeB, 256>>>(ei, batch, pdeg, pflag, E);
    scan_rowptr<<<1, 1024>>>(pdeg, prow, pcur, N);
    fill_csr   <<<edgeB, 256>>>(ei, pcur, pcsr, E);

    // Layer 1 (K=128): y1 = x@Wrel1, rA = x@Wroot1; h1 = relu(gather(y1)+rA)
    dual_gemm<FEAT><<<gemmB, 256>>>(x, Wrel1, Wroot1, py, prA, N);
    gather_agg<0><<<gathB, 256>>>(py4, prow, pdeg, pcsr, pflag, batch, prA4, N);

    // Layer 2 (K=64): y2 = h1@Wrel2, rB = h1@Wroot2; h2 = relu(gather(y2)+rB) on flagged
    dual_gemm<HID><<<gemmB, 256>>>(prA, Wrel2, Wroot2, py, prB, N);
    gather_agg<1><<<gathB, 256>>>(py4, prow, pdeg, pcsr, pflag, batch, prB4, N);

    // Layer 3 (graph-0 prefix): agg3 = gather(h2) into py, then GEMM
    gather_agg<2><<<gathB, 256>>>(prB4, prow, pdeg, pcsr, pflag, batch, py4, N);
    gemm3_prefix<<<gemmB, 256>>>(py, prB, Wrel3, Wroot3, batch, prA, N);

    // Head
    pool_head<<<1, 256>>>(prA, batch, Wfc, bfc, out, N);
}